// round 16
// baseline (speedup 1.0000x reference)
#include <cuda_runtime.h>
#include <cstdint>

#define IC    1024
#define CDIM  256
#define NC    16
#define DD    32
#define CH    64
#define HROWS 512                 // rows per half-batch
#define NCHUNK (HROWS / CH)       // 8
#define RT    512
#define EPS   1e-7f

// ---- device gmem scratch (__device__ globals; no allocation) ----
__device__ float g_w [128 * NC * CDIM];   // per-batch w = W @ out   (16x256)
__device__ float g_vp[256 * NC * CDIM];   // per half-batch v partials
__device__ float g_us[256 * CDIM];        // per half-batch usum partials

// ---- PDL controls ----
#define PDL_TRIGGER() asm volatile("griddepcontrol.launch_dependents;" ::: "memory")
#define PDL_WAIT()    asm volatile("griddepcontrol.wait;" ::: "memory")

// ---- routing-kernel smem layout (float offsets) ----
#define OFF_U     0        // 64*256 = 16384 (single buffer; VPART 2x4096 aliases at 0)
#define OFF_W     16384    // 16*256 = 4096
#define OFF_BLOG  20480    // 8 kg * 64 rows * 16 (rotate-perm n) = 8192
#define OFF_CS    20480    // aliases blog[0..1024) — guarded by intra-softmax barrier
#define RSM_FLOATS 28672
#define RSM_BYTES (RSM_FLOATS * 4)   // 114688 B -> 2 CTAs/SM (229376 <= 228KB)

// ---- packed f32x2 helpers (sm_100+) ----
__device__ __forceinline__ unsigned long long ffma2(unsigned long long a, unsigned long long b,
                                                    unsigned long long c) {
    unsigned long long d;
    asm("fma.rn.f32x2 %0, %1, %2, %3;" : "=l"(d) : "l"(a), "l"(b), "l"(c));
    return d;
}
__device__ __forceinline__ unsigned long long pk2(float v) {
    unsigned long long d; asm("mov.b64 %0, {%1, %1};" : "=l"(d) : "f"(v)); return d;
}
__device__ __forceinline__ float2 upk(unsigned long long d) {
    float2 r; asm("mov.b64 {%0, %1}, %2;" : "=f"(r.x), "=f"(r.y) : "l"(d)); return r;
}

__device__ __forceinline__ void cp16(float* dst, const float* src) {
    unsigned d = (unsigned)__cvta_generic_to_shared(dst);
    asm volatile("cp.async.cg.shared.global [%0], [%1], 16;" :: "r"(d), "l"(src));
}

// 512-thread prefetch of one 64x256 chunk (single buffer, xor-swizzled)
__device__ __forceinline__ void prefetch_chunk(float* sm, const float* u, int chunk, int t) {
    const float* src = u + (size_t)chunk * CH * CDIM;
#pragma unroll
    for (int k = 0; k < 8; k++) {
        int idx = t + k * RT;             // 0..4095
        int row = idx >> 6;
        int c4  = idx & 63;
        cp16(&sm[OFF_U + row * CDIM + ((c4 ^ (row & 15)) << 2)], src + row * CDIM + c4 * 4);
    }
    asm volatile("cp.async.commit_group;");
}

// ================= K0: per-half usum partials (lean, BW-bound) =================
__global__ __launch_bounds__(RT, 4)
void usum_kernel(const float* __restrict__ u_vecs) {
    __shared__ float part[8 * CDIM];
    const int t = threadIdx.x, bid = blockIdx.x;
    const int batch = bid >> 1, half = bid & 1;
    const float* u = u_vecs + (size_t)batch * IC * CDIM + (size_t)half * HROWS * CDIM;
    int c4 = t & 63, rg = t >> 6;
    const float* up = u + (size_t)rg * CDIM + c4 * 4;
    float4 a = make_float4(0.f, 0.f, 0.f, 0.f);
#pragma unroll 8
    for (int i = 0; i < HROWS / 8; i++) {
        float4 v = *(const float4*)(up + (size_t)i * 8 * CDIM);
        a.x += v.x; a.y += v.y; a.z += v.z; a.w += v.w;
    }
    *(float4*)&part[rg * CDIM + c4 * 4] = a;
    __syncthreads();
    if (t < CDIM) {
        float s = 0.f;
#pragma unroll
        for (int r = 0; r < 8; r++) s += part[r * CDIM + t];
        g_us[(size_t)bid * CDIM + t] = s;
    }
    PDL_TRIGGER();
}

// ================= boundary: grid 512 = (batch, n-quad of 4 capsules) =================
// mode 0: vsrc = usum/16 -> g_w ; mode 1: vsrc = v -> g_w ; mode 2: final -> gout
__global__ __launch_bounds__(RT, 4)
void bnd_kernel(const float* __restrict__ W, int mode, float* __restrict__ gout) {
    __shared__ float sv  [4 * CDIM];
    __shared__ float sp  [4][4][33];
    __shared__ float sout[4 * DD];
    __shared__ float sstg[4 * 257];
    const int t = threadIdx.x, wid = t >> 5, lane = t & 31;
    const int b = blockIdx.x >> 2, nq = blockIdx.x & 3;   // capsules nq*4 .. +4

    PDL_TRIGGER();
    PDL_WAIT();

    if (mode == 0) {
        if (t < CDIM)
            sv[t] = (g_us[(size_t)(2 * b) * CDIM + t] + g_us[(size_t)(2 * b + 1) * CDIM + t])
                    * (1.f / 16.f);
    } else {
        if (t < 256) {                    // 256 quads = 4n x 64 quads
            int n = t >> 6, c = (t & 63) * 4;
            size_t off = ((size_t)(nq * 4 + n)) * CDIM + c;
            float4 a = *(const float4*)&g_vp[(size_t)(2 * b) * NC * CDIM + off];
            float4 d = *(const float4*)&g_vp[(size_t)(2 * b + 1) * NC * CDIM + off];
            a.x += d.x; a.y += d.y; a.z += d.z; a.w += d.w;
            *(float4*)&sv[n * CDIM + c] = a;
        }
    }
    __syncthreads();

    // ---- phase 1: warp = (nw in 4, cq in 4); s-partial over 64 c, 16-wide MLP ----
    {
        const int nw = wid & 3, cq = wid >> 2;
        const float* vs = (mode == 0) ? sv : &sv[nw * CDIM];
        const float* Wp = W + (nq * 4 + nw) * DD + lane;
        float a0 = 0.f, a1 = 0.f, a2 = 0.f, a3 = 0.f;
#pragma unroll
        for (int c0 = cq * 64; c0 < cq * 64 + 64; c0 += 16) {
            float wv[16];
#pragma unroll
            for (int j = 0; j < 16; j++) wv[j] = Wp[(c0 + j) * (NC * DD)];
#pragma unroll
            for (int j = 0; j < 16; j++) {
                float p = vs[c0 + j] * wv[j];
                if ((j & 3) == 0) a0 += p; else if ((j & 3) == 1) a1 += p;
                else if ((j & 3) == 2) a2 += p; else a3 += p;
            }
        }
        sp[cq][nw][lane] = (a0 + a1) + (a2 + a3);
    }
    __syncthreads();
    if (wid < 4) {
        float s = (sp[0][wid][lane] + sp[1][wid][lane]) + (sp[2][wid][lane] + sp[3][wid][lane]);
        float ss = s * s;
#pragma unroll
        for (int o = 16; o > 0; o >>= 1) ss += __shfl_xor_sync(0xffffffffu, ss, o);
        float ov = s * rsqrtf(ss + EPS);
        if (mode == 2) gout[(size_t)b * NC * DD + (nq * 4 + wid) * DD + lane] = ov;
        else           sout[wid * DD + lane] = ov;
    }
    if (mode == 2) return;
    __syncthreads();

    // ---- phase 2: w[n][c] = W[c, n*32:+32] . out[n]; warp = 16-c chunk ----
    {
        float so[4];
        {
            float4 v = *(const float4*)&sout[lane * 4];
            so[0] = v.x; so[1] = v.y; so[2] = v.z; so[3] = v.w;
        }
#pragma unroll 4
        for (int i = 0; i < 16; i++) {
            int c = wid * 16 + i;
            float4 q0 = *(const float4*)(W + c * (NC * DD) + nq * 128 + lane * 4);
            float p = q0.x * so[0] + q0.y * so[1] + q0.z * so[2] + q0.w * so[3];
            p += __shfl_xor_sync(0xffffffffu, p, 1);
            p += __shfl_xor_sync(0xffffffffu, p, 2);
            p += __shfl_xor_sync(0xffffffffu, p, 4);
            if ((lane & 7) == 0)
                sstg[(lane >> 3) * 257 + c] = p;
        }
    }
    __syncthreads();
    if (t < 256) {
        int n = t >> 6, c = (t & 63) * 4;
        float4 v = make_float4(sstg[n * 257 + c], sstg[n * 257 + c + 1],
                               sstg[n * 257 + c + 2], sstg[n * 257 + c + 3]);
        *(float4*)&g_w[(size_t)b * NC * CDIM + (nq * 4 + n) * CDIM + c] = v;
    }
}

// ================= routing pass: logits -> softmax -> v partial =================
__global__ __launch_bounds__(RT, 2)
void route_kernel(const float* __restrict__ u_vecs, int rev) {
    extern __shared__ float sm[];
    const int t = threadIdx.x, wid = t >> 5, lane = t & 31;
    const int bid = blockIdx.x, batch = bid >> 1, half = bid & 1;
    const float* u = u_vecs + (size_t)batch * IC * CDIM + (size_t)half * HROWS * CDIM;

    // A roles: warp = (kg in 8 -> 32 ch, nh in 2 -> 8 n); lane -> rows lane, lane+32
    const int a_kg = wid & 7;
    const int a_nh = wid >> 3;
    // C roles: warp = (nh, chq, rgrp); lane = channel-pair within quarter
    const int c_nh   = wid & 1;
    const int c_chq  = (wid >> 1) & 3;
    const int c_rgrp = wid >> 3;
    const int c_c2   = c_chq * 32 + lane;
    const int c_q    = c_c2 >> 1;
    const int c_sub  = (c_c2 & 1) * 2;

    // input-only prologue BEFORE the PDL wait: chunk-0 DMA overlaps predecessor
    prefetch_chunk(sm, u, rev ? (NCHUNK - 1) : 0, t);

    PDL_WAIT();       // g_w (predecessor bnd output) must be visible from here on

    // stage w (16x256); second commit group
    {
        const float* ws = g_w + (size_t)batch * NC * CDIM;
        cp16(&sm[OFF_W + t * 8], ws + t * 8);
        cp16(&sm[OFF_W + t * 8 + 4], ws + t * 8 + 4);
    }
    asm volatile("cp.async.commit_group;");

    unsigned long long vac2[8];
#pragma unroll
    for (int m = 0; m < 8; m++) vac2[m] = 0ull;

    for (int k = 0; k < NCHUNK; ++k) {
        asm volatile("cp.async.wait_group 0;" ::: "memory");
        __syncthreads();
        const float* ub = &sm[OFF_U];

        // --- step A: blog[n][row] partials; 8n x 32ch per warp, 2 rows/lane ---
        {
            const int r0 = lane, r1 = lane + 32;
            const int s0 = r0 & 15, s1 = r1 & 15;
            const float* rb0 = ub + r0 * CDIM;
            const float* rb1 = ub + r1 * CDIM;
            const float* wb = &sm[OFF_W + (a_nh * 8) * CDIM];
            unsigned long long acc[8][2];
#pragma unroll
            for (int m = 0; m < 8; m++) { acc[m][0] = 0ull; acc[m][1] = 0ull; }
#pragma unroll
            for (int j = 0; j < 8; j++) {
                int q = a_kg * 8 + j;
                ulonglong2 uA = *(const ulonglong2*)(rb0 + ((q ^ s0) << 2));
                ulonglong2 uB = *(const ulonglong2*)(rb1 + ((q ^ s1) << 2));
#pragma unroll
                for (int m = 0; m < 8; m++) {
                    ulonglong2 w2 = *(const ulonglong2*)(wb + m * CDIM + q * 4);
                    acc[m][0] = ffma2(uA.x, w2.x, acc[m][0]);
                    acc[m][0] = ffma2(uA.y, w2.y, acc[m][0]);
                    acc[m][1] = ffma2(uB.x, w2.x, acc[m][1]);
                    acc[m][1] = ffma2(uB.y, w2.y, acc[m][1]);
                }
            }
            // store: blog[kg][row][(n + row) & 15] (rotate-perm: stores 2-way, gathers clean)
            float* bb = &sm[OFF_BLOG + a_kg * (64 * 16)];
            const int cb = a_nh * 8;
#pragma unroll
            for (int m = 0; m < 8; m++) {
                float2 f0 = upk(acc[m][0]), f1 = upk(acc[m][1]);
                bb[r0 * 16 + ((cb + m + r0) & 15)] = f0.x + f0.y;
                bb[r1 * 16 + ((cb + m + r1) & 15)] = f1.x + f1.y;
            }
        }
        __syncthreads();

        // --- softmax over n per row; 2 rows/thread; gather 8 kg-partials (perm read) ---
        float cval0, cval1;
        {
            const int n = t & 15, ii0 = t >> 4;
            const int ia = ii0, ib = ii0 + 32;
            float bla = 0.f, blb = 0.f;
#pragma unroll
            for (int kg = 0; kg < 8; kg++) {
                bla += sm[OFF_BLOG + kg * (64 * 16) + ia * 16 + ((n + ia) & 15)];
                blb += sm[OFF_BLOG + kg * (64 * 16) + ib * 16 + ((n + ib) & 15)];
            }
            float ea = __expf(bla), eb = __expf(blb);
            float sa = ea, sb = eb;
#pragma unroll
            for (int o = 8; o > 0; o >>= 1) {
                sa += __shfl_xor_sync(0xffffffffu, sa, o, 16);
                sb += __shfl_xor_sync(0xffffffffu, sb, o, 16);
            }
            cval0 = __fdividef(ea, sa);
            cval1 = __fdividef(eb, sb);
        }
        __syncthreads();   // all blog reads complete before cs overwrites blog[0..1024)
        {
            const int n = t & 15, ii0 = t >> 4;
            sm[OFF_CS + ii0 * 16 + n] = cval0;
            sm[OFF_CS + (ii0 + 32) * 16 + n] = cval1;
        }
        __syncthreads();

        // --- step C: v[n][chpair] += c[n][row]*u[row][chpair]; 8n x 2ch, 32 rows ---
        {
            const float* csb = &sm[OFF_CS + c_nh * 8];
#pragma unroll 4
            for (int r32 = 0; r32 < 32; r32++) {
                int row = c_rgrp * 32 + r32;
                unsigned long long uu =
                    *(const unsigned long long*)(ub + row * CDIM + ((c_q ^ (row & 15)) << 2) + c_sub);
                float4 ca = *(const float4*)(csb + row * NC);
                float4 cb = *(const float4*)(csb + row * NC + 4);
                vac2[0] = ffma2(uu, pk2(ca.x), vac2[0]);
                vac2[1] = ffma2(uu, pk2(ca.y), vac2[1]);
                vac2[2] = ffma2(uu, pk2(ca.z), vac2[2]);
                vac2[3] = ffma2(uu, pk2(ca.w), vac2[3]);
                vac2[4] = ffma2(uu, pk2(cb.x), vac2[4]);
                vac2[5] = ffma2(uu, pk2(cb.y), vac2[5]);
                vac2[6] = ffma2(uu, pk2(cb.z), vac2[6]);
                vac2[7] = ffma2(uu, pk2(cb.w), vac2[7]);
            }
        }
        __syncthreads();
        if (k + 1 < NCHUNK) prefetch_chunk(sm, u, rev ? (NCHUNK - 2 - k) : (k + 1), t);
    }

    PDL_TRIGGER();    // main loop done: successor may pre-launch into our epilogue

    // dump 2 rgrp copies into chunk buffer (dead), reduce, STG partial v
    {
#pragma unroll
        for (int m = 0; m < 8; m++) {
            int n = c_nh * 8 + m;
            *(unsigned long long*)&sm[OFF_U + c_rgrp * (NC * CDIM) + n * CDIM + c_c2 * 2] = vac2[m];
        }
    }
    __syncthreads();
    {
        float* dst = g_vp + (size_t)bid * NC * CDIM;
        for (int q = t; q < NC * CDIM / 4; q += RT) {
            float4 a = *(float4*)&sm[OFF_U + 4 * q];
            float4 b = *(float4*)&sm[OFF_U + NC * CDIM + 4 * q];
            a.x += b.x; a.y += b.y; a.z += b.z; a.w += b.w;
            *(float4*)&dst[4 * q] = a;
        }
    }
}

extern "C" void kernel_launch(void* const* d_in, const int* in_sizes, int n_in,
                              void* d_out, int out_size) {
    const float* u_vecs = (const float*)d_in[0];   // (128, 1024, 256) fp32
    const float* W      = (const float*)d_in[1];   // (256, 512) fp32
    float* out          = (float*)d_out;           // (128, 16, 32) fp32

    cudaFuncSetAttribute(route_kernel, cudaFuncAttributeMaxDynamicSharedMemorySize, RSM_BYTES);

    cudaLaunchAttribute at[1];
    at[0].id = cudaLaunchAttributeProgrammaticStreamSerialization;
    at[0].val.programmaticStreamSerializationAllowed = 1;

    cudaLaunchConfig_t cfg{};
    cfg.blockDim = dim3(RT);
    cfg.stream = 0;
    cfg.attrs = at; cfg.numAttrs = 1;

    int m0 = 0, m1 = 1, m2 = 2, rev1 = 1, rev0 = 0;
    float* nullp = nullptr;

    cfg.gridDim = dim3(256); cfg.dynamicSmemBytes = 0;
    cudaLaunchKernelEx(&cfg, usum_kernel, u_vecs);

    cfg.gridDim = dim3(512);
    cudaLaunchKernelEx(&cfg, bnd_kernel, W, m0, nullp);           // bnd0 -> g_w

    cfg.gridDim = dim3(256); cfg.dynamicSmemBytes = RSM_BYTES;
    cudaLaunchKernelEx(&cfg, route_kernel, u_vecs, rev1);         // pass 1 (rev) -> g_vp

    cfg.gridDim = dim3(512); cfg.dynamicSmemBytes = 0;
    cudaLaunchKernelEx(&cfg, bnd_kernel, W, m1, nullp);           // bnd1 -> g_w

    cfg.gridDim = dim3(256); cfg.dynamicSmemBytes = RSM_BYTES;
    cudaLaunchKernelEx(&cfg, route_kernel, u_vecs, rev0);         // pass 2 (fwd) -> g_vp

    cfg.gridDim = dim3(512); cfg.dynamicSmemBytes = 0;
    cudaLaunchKernelEx(&cfg, bnd_kernel, W, m2, out);             // final -> d_out
}

// round 17
// speedup vs baseline: 1.0494x; 1.0494x over previous
#include <cuda_runtime.h>
#include <cstdint>

#define IC    1024
#define CDIM  256
#define NC    16
#define DD    32
#define CH    64
#define HROWS 512                 // rows per half-batch
#define NCHUNK (HROWS / CH)       // 8
#define RT    512
#define EPS   1e-7f

// ---- device gmem scratch (__device__ globals; no allocation) ----
__device__ float g_w [128 * NC * CDIM];   // per-batch w = W @ out   (16x256)
__device__ float g_vp[256 * NC * CDIM];   // per half-batch v partials
__device__ float g_us[256 * CDIM];        // per half-batch usum partials

// ---- PDL controls ----
#define PDL_TRIGGER() asm volatile("griddepcontrol.launch_dependents;" ::: "memory")
#define PDL_WAIT()    asm volatile("griddepcontrol.wait;" ::: "memory")

// ---- routing-kernel smem layout (float offsets) ----
#define OFF_U     0        // 64*256 = 16384 (single buffer; VPART 2x4096 aliases at 0)
#define OFF_W     16384    // 16*256 = 4096
#define OFF_BLOG  20480    // 4 kg * 64 rows * 17 = 4352
#define OFF_CS    24832    // 64 * 16 = 1024
#define RSM_FLOATS 25856
#define RSM_BYTES (RSM_FLOATS * 4)   // 103424 B -> 2 CTAs/SM

// ---- packed f32x2 helpers (sm_100+) ----
__device__ __forceinline__ unsigned long long ffma2(unsigned long long a, unsigned long long b,
                                                    unsigned long long c) {
    unsigned long long d;
    asm("fma.rn.f32x2 %0, %1, %2, %3;" : "=l"(d) : "l"(a), "l"(b), "l"(c));
    return d;
}
__device__ __forceinline__ unsigned long long pk2(float v) {
    unsigned long long d; asm("mov.b64 %0, {%1, %1};" : "=l"(d) : "f"(v)); return d;
}
__device__ __forceinline__ float2 upk(unsigned long long d) {
    float2 r; asm("mov.b64 {%0, %1}, %2;" : "=f"(r.x), "=f"(r.y) : "l"(d)); return r;
}

__device__ __forceinline__ void cp16(float* dst, const float* src) {
    unsigned d = (unsigned)__cvta_generic_to_shared(dst);
    asm volatile("cp.async.cg.shared.global [%0], [%1], 16;" :: "r"(d), "l"(src));
}

// 512-thread prefetch of one 64x256 chunk (single buffer, xor-swizzled)
__device__ __forceinline__ void prefetch_chunk(float* sm, const float* u, int chunk, int t) {
    const float* src = u + (size_t)chunk * CH * CDIM;
#pragma unroll
    for (int k = 0; k < 8; k++) {
        int idx = t + k * RT;             // 0..4095
        int row = idx >> 6;
        int c4  = idx & 63;
        cp16(&sm[OFF_U + row * CDIM + ((c4 ^ (row & 15)) << 2)], src + row * CDIM + c4 * 4);
    }
    asm volatile("cp.async.commit_group;");
}

// ================= K0: per-half usum partials (lean, BW-bound) =================
__global__ __launch_bounds__(RT, 4)
void usum_kernel(const float* __restrict__ u_vecs) {
    __shared__ float part[8 * CDIM];
    const int t = threadIdx.x, bid = blockIdx.x;
    const int batch = bid >> 1, half = bid & 1;
    const float* u = u_vecs + (size_t)batch * IC * CDIM + (size_t)half * HROWS * CDIM;
    int c4 = t & 63, rg = t >> 6;
    const float* up = u + (size_t)rg * CDIM + c4 * 4;
    float4 a = make_float4(0.f, 0.f, 0.f, 0.f);
#pragma unroll 8
    for (int i = 0; i < HROWS / 8; i++) {
        float4 v = *(const float4*)(up + (size_t)i * 8 * CDIM);
        a.x += v.x; a.y += v.y; a.z += v.z; a.w += v.w;
    }
    *(float4*)&part[rg * CDIM + c4 * 4] = a;
    __syncthreads();
    if (t < CDIM) {
        float s = 0.f;
#pragma unroll
        for (int r = 0; r < 8; r++) s += part[r * CDIM + t];
        g_us[(size_t)bid * CDIM + t] = s;
    }
    PDL_TRIGGER();
}

// ================= boundary: grid 512 = (batch, n-quad of 4 capsules) =================
// mode 0: vsrc = usum/16 -> g_w ; mode 1: vsrc = v -> g_w ; mode 2: final -> gout
__global__ __launch_bounds__(RT, 4)
void bnd_kernel(const float* __restrict__ W, int mode, float* __restrict__ gout) {
    __shared__ float sv  [4 * CDIM];
    __shared__ float sp  [4][4][33];
    __shared__ float sout[4 * DD];
    __shared__ float sstg[4 * 257];
    const int t = threadIdx.x, wid = t >> 5, lane = t & 31;
    const int b = blockIdx.x >> 2, nq = blockIdx.x & 3;   // capsules nq*4 .. +4

    PDL_TRIGGER();
    PDL_WAIT();

    if (mode == 0) {
        if (t < CDIM)
            sv[t] = (g_us[(size_t)(2 * b) * CDIM + t] + g_us[(size_t)(2 * b + 1) * CDIM + t])
                    * (1.f / 16.f);
    } else {
        if (t < 256) {                    // 256 quads = 4n x 64 quads
            int n = t >> 6, c = (t & 63) * 4;
            size_t off = ((size_t)(nq * 4 + n)) * CDIM + c;
            float4 a = *(const float4*)&g_vp[(size_t)(2 * b) * NC * CDIM + off];
            float4 d = *(const float4*)&g_vp[(size_t)(2 * b + 1) * NC * CDIM + off];
            a.x += d.x; a.y += d.y; a.z += d.z; a.w += d.w;
            *(float4*)&sv[n * CDIM + c] = a;
        }
    }
    __syncthreads();

    // ---- phase 1: warp = (nw in 4, cq in 4); s-partial over 64 c, 16-wide MLP ----
    {
        const int nw = wid & 3, cq = wid >> 2;
        const float* vs = (mode == 0) ? sv : &sv[nw * CDIM];
        const float* Wp = W + (nq * 4 + nw) * DD + lane;
        float a0 = 0.f, a1 = 0.f, a2 = 0.f, a3 = 0.f;
#pragma unroll
        for (int c0 = cq * 64; c0 < cq * 64 + 64; c0 += 16) {
            float wv[16];
#pragma unroll
            for (int j = 0; j < 16; j++) wv[j] = Wp[(c0 + j) * (NC * DD)];
#pragma unroll
            for (int j = 0; j < 16; j++) {
                float p = vs[c0 + j] * wv[j];
                if ((j & 3) == 0) a0 += p; else if ((j & 3) == 1) a1 += p;
                else if ((j & 3) == 2) a2 += p; else a3 += p;
            }
        }
        sp[cq][nw][lane] = (a0 + a1) + (a2 + a3);
    }
    __syncthreads();
    if (wid < 4) {
        float s = (sp[0][wid][lane] + sp[1][wid][lane]) + (sp[2][wid][lane] + sp[3][wid][lane]);
        float ss = s * s;
#pragma unroll
        for (int o = 16; o > 0; o >>= 1) ss += __shfl_xor_sync(0xffffffffu, ss, o);
        float ov = s * rsqrtf(ss + EPS);
        if (mode == 2) gout[(size_t)b * NC * DD + (nq * 4 + wid) * DD + lane] = ov;
        else           sout[wid * DD + lane] = ov;
    }
    if (mode == 2) return;
    __syncthreads();

    // ---- phase 2: w[n][c] = W[c, n*32:+32] . out[n]; warp = 16-c chunk ----
    {
        float so[4];
        {
            float4 v = *(const float4*)&sout[lane * 4];
            so[0] = v.x; so[1] = v.y; so[2] = v.z; so[3] = v.w;
        }
#pragma unroll 4
        for (int i = 0; i < 16; i++) {
            int c = wid * 16 + i;
            float4 q0 = *(const float4*)(W + c * (NC * DD) + nq * 128 + lane * 4);
            float p = q0.x * so[0] + q0.y * so[1] + q0.z * so[2] + q0.w * so[3];
            p += __shfl_xor_sync(0xffffffffu, p, 1);
            p += __shfl_xor_sync(0xffffffffu, p, 2);
            p += __shfl_xor_sync(0xffffffffu, p, 4);
            if ((lane & 7) == 0)
                sstg[(lane >> 3) * 257 + c] = p;
        }
    }
    __syncthreads();
    if (t < 256) {
        int n = t >> 6, c = (t & 63) * 4;
        float4 v = make_float4(sstg[n * 257 + c], sstg[n * 257 + c + 1],
                               sstg[n * 257 + c + 2], sstg[n * 257 + c + 3]);
        *(float4*)&g_w[(size_t)b * NC * CDIM + (nq * 4 + n) * CDIM + c] = v;
    }
}

// ================= routing pass: logits -> softmax -> v partial =================
__global__ __launch_bounds__(RT, 2)
void route_kernel(const float* __restrict__ u_vecs, int rev) {
    extern __shared__ float sm[];
    const int t = threadIdx.x, wid = t >> 5, lane = t & 31;
    const int bid = blockIdx.x, batch = bid >> 1, half = bid & 1;
    const float* u = u_vecs + (size_t)batch * IC * CDIM + (size_t)half * HROWS * CDIM;

    // A roles: warp = (kg in 4 -> 64 ch, nh in 4 -> 4 n); lane -> rows lane, lane+32
    const int a_kg = wid & 3;
    const int a_nh = wid >> 2;
    // C roles: warp = (nh, chq, rgrp); lane = channel-pair within quarter
    const int c_nh   = wid & 1;
    const int c_chq  = (wid >> 1) & 3;
    const int c_rgrp = wid >> 3;
    const int c_c2   = c_chq * 32 + lane;
    const int c_q    = c_c2 >> 1;
    const int c_sub  = (c_c2 & 1) * 2;

    // input-only prologue BEFORE the PDL wait: chunk-0 DMA overlaps predecessor
    prefetch_chunk(sm, u, rev ? (NCHUNK - 1) : 0, t);

    PDL_WAIT();       // g_w (predecessor bnd output) must be visible from here on

    // stage w (16x256); second commit group
    {
        const float* ws = g_w + (size_t)batch * NC * CDIM;
        cp16(&sm[OFF_W + t * 8], ws + t * 8);
        cp16(&sm[OFF_W + t * 8 + 4], ws + t * 8 + 4);
    }
    asm volatile("cp.async.commit_group;");

    unsigned long long vac2[8];
#pragma unroll
    for (int m = 0; m < 8; m++) vac2[m] = 0ull;

    for (int k = 0; k < NCHUNK; ++k) {
        asm volatile("cp.async.wait_group 0;" ::: "memory");
        __syncthreads();
        const float* ub = &sm[OFF_U];

        // --- step A: blog[n][row] partials; 4n x 64ch per warp, 2 rows/lane ---
        {
            const int r0 = lane, r1 = lane + 32;
            const int s0 = r0 & 15, s1 = r1 & 15;
            const float* rb0 = ub + r0 * CDIM;
            const float* rb1 = ub + r1 * CDIM;
            const float* wb = &sm[OFF_W + (a_nh * 4) * CDIM];
            unsigned long long acc[4][2];
#pragma unroll
            for (int m = 0; m < 4; m++) { acc[m][0] = 0ull; acc[m][1] = 0ull; }
#pragma unroll
            for (int j = 0; j < 16; j++) {
                int q = a_kg * 16 + j;
                ulonglong2 uA = *(const ulonglong2*)(rb0 + ((q ^ s0) << 2));
                ulonglong2 uB = *(const ulonglong2*)(rb1 + ((q ^ s1) << 2));
#pragma unroll
                for (int m = 0; m < 4; m++) {
                    ulonglong2 w2 = *(const ulonglong2*)(wb + m * CDIM + q * 4);
                    acc[m][0] = ffma2(uA.x, w2.x, acc[m][0]);
                    acc[m][0] = ffma2(uA.y, w2.y, acc[m][0]);
                    acc[m][1] = ffma2(uB.x, w2.x, acc[m][1]);
                    acc[m][1] = ffma2(uB.y, w2.y, acc[m][1]);
                }
            }
            float* bb = &sm[OFF_BLOG + a_kg * (64 * 17) + a_nh * 4];
#pragma unroll
            for (int m = 0; m < 4; m++) {
                float2 f0 = upk(acc[m][0]), f1 = upk(acc[m][1]);
                bb[r0 * 17 + m] = f0.x + f0.y;
                bb[r1 * 17 + m] = f1.x + f1.y;
            }
        }
        __syncthreads();

        // --- softmax over n per row; 2 rows/thread; no max-subtract (range-safe) ---
        {
            const int n = t & 15, ii0 = t >> 4;
#pragma unroll
            for (int s2 = 0; s2 < 2; s2++) {
                int ii = ii0 + s2 * 32;
                float bl = 0.f;
#pragma unroll
                for (int kg = 0; kg < 4; kg++)
                    bl += sm[OFF_BLOG + kg * (64 * 17) + ii * 17 + n];
                float e = __expf(bl);
                float ssum = e;
#pragma unroll
                for (int o = 8; o > 0; o >>= 1) ssum += __shfl_xor_sync(0xffffffffu, ssum, o, 16);
                sm[OFF_CS + ii * NC + n] = __fdividef(e, ssum);
            }
        }
        __syncthreads();

        // --- step C: v[n][chpair] += c[n][row]*u[row][chpair]; 8n x 2ch, 32 rows ---
        {
            const float* csb = &sm[OFF_CS + c_nh * 8];
#pragma unroll
            for (int r32 = 0; r32 < 32; r32++) {
                int row = c_rgrp * 32 + r32;
                unsigned long long uu =
                    *(const unsigned long long*)(ub + row * CDIM + ((c_q ^ (row & 15)) << 2) + c_sub);
                float4 ca = *(const float4*)(csb + row * NC);
                float4 cb = *(const float4*)(csb + row * NC + 4);
                vac2[0] = ffma2(uu, pk2(ca.x), vac2[0]);
                vac2[1] = ffma2(uu, pk2(ca.y), vac2[1]);
                vac2[2] = ffma2(uu, pk2(ca.z), vac2[2]);
                vac2[3] = ffma2(uu, pk2(ca.w), vac2[3]);
                vac2[4] = ffma2(uu, pk2(cb.x), vac2[4]);
                vac2[5] = ffma2(uu, pk2(cb.y), vac2[5]);
                vac2[6] = ffma2(uu, pk2(cb.z), vac2[6]);
                vac2[7] = ffma2(uu, pk2(cb.w), vac2[7]);
            }
        }
        __syncthreads();
        if (k + 1 < NCHUNK) prefetch_chunk(sm, u, rev ? (NCHUNK - 2 - k) : (k + 1), t);
    }

    PDL_TRIGGER();    // main loop done: successor may pre-launch into our epilogue

    // dump 2 rgrp copies into chunk buffer (dead), reduce, STG partial v
    {
#pragma unroll
        for (int m = 0; m < 8; m++) {
            int n = c_nh * 8 + m;
            *(unsigned long long*)&sm[OFF_U + c_rgrp * (NC * CDIM) + n * CDIM + c_c2 * 2] = vac2[m];
        }
    }
    __syncthreads();
    {
        float* dst = g_vp + (size_t)bid * NC * CDIM;
        for (int q = t; q < NC * CDIM / 4; q += RT) {
            float4 a = *(float4*)&sm[OFF_U + 4 * q];
            float4 b = *(float4*)&sm[OFF_U + NC * CDIM + 4 * q];
            a.x += b.x; a.y += b.y; a.z += b.z; a.w += b.w;
            *(float4*)&dst[4 * q] = a;
        }
    }
}

extern "C" void kernel_launch(void* const* d_in, const int* in_sizes, int n_in,
                              void* d_out, int out_size) {
    const float* u_vecs = (const float*)d_in[0];   // (128, 1024, 256) fp32
    const float* W      = (const float*)d_in[1];   // (256, 512) fp32
    float* out          = (float*)d_out;           // (128, 16, 32) fp32

    cudaFuncSetAttribute(route_kernel, cudaFuncAttributeMaxDynamicSharedMemorySize, RSM_BYTES);

    cudaLaunchAttribute at[1];
    at[0].id = cudaLaunchAttributeProgrammaticStreamSerialization;
    at[0].val.programmaticStreamSerializationAllowed = 1;

    cudaLaunchConfig_t cfg{};
    cfg.blockDim = dim3(RT);
    cfg.stream = 0;
    cfg.attrs = at; cfg.numAttrs = 1;

    int m0 = 0, m1 = 1, m2 = 2, rev1 = 1, rev0 = 0;
    float* nullp = nullptr;

    cfg.gridDim = dim3(256); cfg.dynamicSmemBytes = 0;
    cudaLaunchKernelEx(&cfg, usum_kernel, u_vecs);

    cfg.gridDim = dim3(512);
    cudaLaunchKernelEx(&cfg, bnd_kernel, W, m0, nullp);           // bnd0 -> g_w

    cfg.gridDim = dim3(256); cfg.dynamicSmemBytes = RSM_BYTES;
    cudaLaunchKernelEx(&cfg, route_kernel, u_vecs, rev1);         // pass 1 (rev) -> g_vp

    cfg.gridDim = dim3(512); cfg.dynamicSmemBytes = 0;
    cudaLaunchKernelEx(&cfg, bnd_kernel, W, m1, nullp);           // bnd1 -> g_w

    cfg.gridDim = dim3(256); cfg.dynamicSmemBytes = RSM_BYTES;
    cudaLaunchKernelEx(&cfg, route_kernel, u_vecs, rev0);         // pass 2 (fwd) -> g_vp

    cfg.gridDim = dim3(512); cfg.dynamicSmemBytes = 0;
    cudaLaunchKernelEx(&cfg, bnd_kernel, W, m2, out);             // final -> d_out
}